// round 8
// baseline (speedup 1.0000x reference)
#include <cuda_runtime.h>
#include <math.h>

// Problem constants
#define NB 128   // batch
#define TS 512   // timesteps
#define DI 512   // input dim
#define HD 512   // hidden dim

// ---------------- packed f32x2 helpers (sm_100+ FFMA2 path) ----------------
__device__ __forceinline__ void fma2(unsigned long long& acc,
                                     unsigned long long a,
                                     unsigned long long b) {
    asm("fma.rn.f32x2 %0, %1, %2, %0;" : "+l"(acc) : "l"(a), "l"(b));
}

__device__ __forceinline__ void unpack2(unsigned long long v, float& lo, float& hi) {
    unsigned int a, b;
    asm("mov.b64 {%0, %1}, %2;" : "=r"(a), "=r"(b) : "l"(v));
    lo = __uint_as_float(a);
    hi = __uint_as_float(b);
}

#define CLUSTER_ARRIVE() asm volatile("barrier.cluster.arrive.aligned;" ::: "memory")
#define CLUSTER_WAIT()   asm volatile("barrier.cluster.wait.aligned;" ::: "memory")

// ---------------------------------------------------------------------------
// Kernel 1: xW = x @ Wx + b  (A:[65536,512] @ B:[512,512] -> C:[65536,512])
// (unchanged from R4 — passed with rel_err 3.7e-7)
// ---------------------------------------------------------------------------
__global__ __launch_bounds__(256) void xw_gemm(
    const float* __restrict__ A,
    const float* __restrict__ B,
    const float* __restrict__ bias,
    float* __restrict__ C)
{
    __shared__ float2 As2[128][16];   // [m][k], each entry = (a, a)
    __shared__ float  Bs[16][128];    // [k][n]

    const int m0  = blockIdx.y * 128;
    const int n0  = blockIdx.x * 128;
    const int tid = threadIdx.x;
    const int tn  = tid & 15;
    const int tm  = tid >> 4;

    unsigned long long acc[8][4];
#pragma unroll
    for (int i = 0; i < 8; i++)
#pragma unroll
        for (int j = 0; j < 4; j++) acc[i][j] = 0ULL;

    for (int k0 = 0; k0 < DI; k0 += 16) {
#pragma unroll
        for (int j = 0; j < 2; j++) {
            int f  = tid + j * 256;
            int m  = f >> 2;
            int kq = f & 3;
            float4 v = *(const float4*)(A + (size_t)(m0 + m) * DI + k0 + kq * 4);
            *(float4*)(&As2[m][kq * 4])     = make_float4(v.x, v.x, v.y, v.y);
            *(float4*)(&As2[m][kq * 4 + 2]) = make_float4(v.z, v.z, v.w, v.w);
        }
#pragma unroll
        for (int j = 0; j < 2; j++) {
            int f  = tid + j * 256;
            int k  = f >> 5;
            int nq = f & 31;
            *(float4*)(&Bs[k][nq * 4]) =
                *(const float4*)(B + (size_t)(k0 + k) * HD + n0 + nq * 4);
        }
        __syncthreads();

#pragma unroll
        for (int k = 0; k < 16; k++) {
            ulonglong2 b01 = *(const ulonglong2*)(&Bs[k][tn * 8]);
            ulonglong2 b23 = *(const ulonglong2*)(&Bs[k][tn * 8 + 4]);
#pragma unroll
            for (int i = 0; i < 8; i++) {
                unsigned long long a =
                    *(const unsigned long long*)(&As2[tm * 8 + i][k]);
                fma2(acc[i][0], a, b01.x);
                fma2(acc[i][1], a, b01.y);
                fma2(acc[i][2], a, b23.x);
                fma2(acc[i][3], a, b23.y);
            }
        }
        __syncthreads();
    }

    const float4 bb0 = *(const float4*)(bias + n0 + tn * 8);
    const float4 bb1 = *(const float4*)(bias + n0 + tn * 8 + 4);
#pragma unroll
    for (int i = 0; i < 8; i++) {
        float r0, r1, r2, r3, r4, r5, r6, r7;
        unpack2(acc[i][0], r0, r1);
        unpack2(acc[i][1], r2, r3);
        unpack2(acc[i][2], r4, r5);
        unpack2(acc[i][3], r6, r7);
        float* p = C + (size_t)(m0 + tm * 8 + i) * HD + n0 + tn * 8;
        *(float4*)p       = make_float4(r0 + bb0.x, r1 + bb0.y, r2 + bb0.z, r3 + bb0.w);
        *(float4*)(p + 4) = make_float4(r4 + bb1.x, r5 + bb1.y, r6 + bb1.z, r7 + bb1.w);
    }
}

// ---------------------------------------------------------------------------
// Kernel 2: persistent recurrence. ALL 512 timesteps in one launch.
//
// Grid: 16 clusters (y) x 8 CTAs/cluster (x) = 128 blocks, 128 threads each.
// Cluster y owns batch rows [8y, 8y+8); CTA x within the cluster owns hidden
// cols [64x, 64x+64). The dependency closure of a row-group is exactly its
// 8-CTA cluster, so barrier.cluster (HW, ~400cyc) replaces per-step kernel
// launches, and the 16 clusters run fully decoupled.
//
// Wh slice [512][64] (128KB) lives in smem for the whole kernel.
// h_{t-1} rows (8x512) are staged per step as duplicated float2 (33KB) so the
// inner loop is LDS.64 + LDS.128 + 2xFFMA2 per k = issue/smem floor.
// ---------------------------------------------------------------------------
#define HP 514                       // padded Hs row (float2): 4112B -> rows on distinct banks
#define SMEM_WS_BYTES (512 * 64 * 4)               // 131072
#define SMEM_RNN_BYTES (SMEM_WS_BYTES + 8 * HP * 8) // +32896 = 163968

__global__ __launch_bounds__(128, 1) __cluster_dims__(8, 1, 1)
void rnn_persistent(const float* __restrict__ Wh,
                    const float* __restrict__ h0,
                    float* __restrict__ out)
{
    extern __shared__ char smem[];
    float*  Ws = (float*)smem;                         // [512][64]
    float2* Hs = (float2*)(smem + SMEM_WS_BYTES);      // [8][HP] duplicated

    const int tid = threadIdx.x;
    const int m0  = blockIdx.y * 8;    // batch-row base
    const int n0  = blockIdx.x * 64;   // hidden-col base

    // ---- load Wh slice once: 512x64 floats = 8192 float4, 64 per thread ----
#pragma unroll 8
    for (int j = 0; j < 64; j++) {
        int f  = tid + j * 128;
        int k  = f >> 4;
        int nq = f & 15;
        *(float4*)(Ws + k * 64 + nq * 4) =
            *(const float4*)(Wh + (size_t)k * HD + n0 + nq * 4);
    }

    // compute-thread mapping: warp = n-quarter, lane&7 = row, lane>>3 = col grp
    const int lane = tid & 31;
    const int wrp  = tid >> 5;
    const int r    = lane & 7;                 // 0..7   (row in tile)
    const int c    = wrp * 16 + (lane >> 3) * 4;  // 0..63 (col in tile)

    // staging mapping: 16 threads per row, 8 float4 each
    const int srow = tid >> 4;                 // 0..7
    const int sq   = tid & 15;

    const float2* hrow = Hs + r * HP;
    const float*  wcol = Ws + c;

    for (int t = 0; t < TS; t++) {
        // ---- stage h_{t-1} rows into smem (duplicated pairs) ----
        const float* src = (t == 0)
            ? (h0 + (size_t)(m0 + srow) * HD)
            : (out + ((size_t)(m0 + srow) * TS + (t - 1)) * HD);
        float2* drow = Hs + srow * HP;
#pragma unroll
        for (int j = 0; j < 8; j++) {
            int q = sq + j * 16;
            float4 v = *(const float4*)(src + q * 4);
            *(float4*)(drow + q * 4)     = make_float4(v.x, v.x, v.y, v.y);
            *(float4*)(drow + q * 4 + 2) = make_float4(v.z, v.z, v.w, v.w);
        }

        // prefetch xw_t for this thread's 4 outputs (independent of Hs)
        float* pio = out + ((size_t)(m0 + r) * TS + t) * HD + n0 + c;
        float4 xw = *(const float4*)pio;

        __syncthreads();

        // ---- h_{t-1} @ Wh : 4 outputs/thread, even/odd k chains ----
        unsigned long long a0 = 0ULL, a1 = 0ULL, b0 = 0ULL, b1 = 0ULL;
#pragma unroll 8
        for (int k = 0; k < HD; k += 2) {
            unsigned long long h0v = *(const unsigned long long*)(hrow + k);
            ulonglong2 w0 = *(const ulonglong2*)(wcol + (size_t)k * 64);
            fma2(a0, h0v, w0.x);
            fma2(a1, h0v, w0.y);
            unsigned long long h1v = *(const unsigned long long*)(hrow + k + 1);
            ulonglong2 w1 = *(const ulonglong2*)(wcol + (size_t)(k + 1) * 64);
            fma2(b0, h1v, w1.x);
            fma2(b1, h1v, w1.y);
        }

        float e0, e1, e2, e3, o0, o1, o2, o3;
        unpack2(a0, e0, e1);
        unpack2(a1, e2, e3);
        unpack2(b0, o0, o1);
        unpack2(b1, o2, o3);

        float4 hv;
        hv.x = tanhf(xw.x + e0 + o0);
        hv.y = tanhf(xw.y + e1 + o1);
        hv.z = tanhf(xw.z + e2 + o2);
        hv.w = tanhf(xw.w + e3 + o3);
        *(float4*)pio = hv;

        // ---- cluster-wide step barrier (also a full block barrier) ----
        __threadfence();
        CLUSTER_ARRIVE();
        CLUSTER_WAIT();
    }
}

// ---------------------------------------------------------------------------
// Launch: xW into d_out, then ONE persistent kernel for all 512 steps.
// ---------------------------------------------------------------------------
extern "C" void kernel_launch(void* const* d_in, const int* in_sizes, int n_in,
                              void* d_out, int out_size) {
    (void)in_sizes; (void)n_in; (void)out_size;
    const float* x  = (const float*)d_in[0];   // [128, 512, 512]
    const float* h0 = (const float*)d_in[1];   // [128, 512]
    const float* Wx = (const float*)d_in[2];   // [512, 512]
    const float* Wh = (const float*)d_in[3];   // [512, 512]
    const float* b  = (const float*)d_in[4];   // [512]
    float* out = (float*)d_out;                // [128, 512, 512]

    dim3 gx(HD / 128, (NB * TS) / 128);        // (4, 512)
    xw_gemm<<<gx, 256>>>(x, Wx, b, out);

    static int smem_set = 0;
    if (!smem_set) {
        cudaFuncSetAttribute(rnn_persistent,
                             cudaFuncAttributeMaxDynamicSharedMemorySize,
                             SMEM_RNN_BYTES);
        smem_set = 1;
    }
    dim3 gs(8, NB / 8);                        // 8 CTAs/cluster x 16 clusters
    rnn_persistent<<<gs, 128, SMEM_RNN_BYTES>>>(Wh, h0, out);
}

// round 11
// speedup vs baseline: 1.7414x; 1.7414x over previous
#include <cuda_runtime.h>
#include <math.h>
#include <stdint.h>

// Problem constants
#define NB 128   // batch
#define TS 512   // timesteps
#define DI 512   // input dim
#define HD 512   // hidden dim

typedef unsigned long long ull;

// ---------------- packed f32x2 helpers (sm_100+ FFMA2 path) ----------------
__device__ __forceinline__ void fma2(ull& acc, ull a, ull b) {
    asm("fma.rn.f32x2 %0, %1, %2, %0;" : "+l"(acc) : "l"(a), "l"(b));
}
__device__ __forceinline__ void add2(ull& a, ull b) {
    asm("add.rn.f32x2 %0, %0, %1;" : "+l"(a) : "l"(b));
}
__device__ __forceinline__ void unpack2(ull v, float& lo, float& hi) {
    unsigned int a, b;
    asm("mov.b64 {%0, %1}, %2;" : "=r"(a), "=r"(b) : "l"(v));
    lo = __uint_as_float(a);
    hi = __uint_as_float(b);
}

#define CLUSTER_ARRIVE() asm volatile("barrier.cluster.arrive.aligned;" ::: "memory")
#define CLUSTER_WAIT()   asm volatile("barrier.cluster.wait.aligned;" ::: "memory")

__device__ __forceinline__ uint32_t smem_u32(const void* p) {
    uint32_t a;
    asm("{ .reg .u64 t; cvta.to.shared.u64 t, %1; cvt.u32.u64 %0, t; }"
        : "=r"(a) : "l"(p));
    return a;
}
__device__ __forceinline__ uint32_t mapa_rank(uint32_t laddr, uint32_t rank) {
    uint32_t r;
    asm("mapa.shared::cluster.u32 %0, %1, %2;" : "=r"(r) : "r"(laddr), "r"(rank));
    return r;
}
__device__ __forceinline__ uint4 ld_cluster_v4(uint32_t addr) {
    uint4 v;
    asm volatile("ld.shared::cluster.v4.b32 {%0,%1,%2,%3}, [%4];"
                 : "=r"(v.x), "=r"(v.y), "=r"(v.z), "=r"(v.w) : "r"(addr));
    return v;
}

// ---------------------------------------------------------------------------
// Kernel 1: xW = x @ Wx + b  (unchanged — proven, rel_err 3.7e-7)
// ---------------------------------------------------------------------------
__global__ __launch_bounds__(256) void xw_gemm(
    const float* __restrict__ A,
    const float* __restrict__ B,
    const float* __restrict__ bias,
    float* __restrict__ C)
{
    __shared__ float2 As2[128][16];
    __shared__ float  Bs[16][128];

    const int m0  = blockIdx.y * 128;
    const int n0  = blockIdx.x * 128;
    const int tid = threadIdx.x;
    const int tn  = tid & 15;
    const int tm  = tid >> 4;

    ull acc[8][4];
#pragma unroll
    for (int i = 0; i < 8; i++)
#pragma unroll
        for (int j = 0; j < 4; j++) acc[i][j] = 0ULL;

    for (int k0 = 0; k0 < DI; k0 += 16) {
#pragma unroll
        for (int j = 0; j < 2; j++) {
            int f  = tid + j * 256;
            int m  = f >> 2;
            int kq = f & 3;
            float4 v = *(const float4*)(A + (size_t)(m0 + m) * DI + k0 + kq * 4);
            *(float4*)(&As2[m][kq * 4])     = make_float4(v.x, v.x, v.y, v.y);
            *(float4*)(&As2[m][kq * 4 + 2]) = make_float4(v.z, v.z, v.w, v.w);
        }
#pragma unroll
        for (int j = 0; j < 2; j++) {
            int f  = tid + j * 256;
            int k  = f >> 5;
            int nq = f & 31;
            *(float4*)(&Bs[k][nq * 4]) =
                *(const float4*)(B + (size_t)(k0 + k) * HD + n0 + nq * 4);
        }
        __syncthreads();

#pragma unroll
        for (int k = 0; k < 16; k++) {
            ulonglong2 b01 = *(const ulonglong2*)(&Bs[k][tn * 8]);
            ulonglong2 b23 = *(const ulonglong2*)(&Bs[k][tn * 8 + 4]);
#pragma unroll
            for (int i = 0; i < 8; i++) {
                ull a = *(const ull*)(&As2[tm * 8 + i][k]);
                fma2(acc[i][0], a, b01.x);
                fma2(acc[i][1], a, b01.y);
                fma2(acc[i][2], a, b23.x);
                fma2(acc[i][3], a, b23.y);
            }
        }
        __syncthreads();
    }

    const float4 bb0 = *(const float4*)(bias + n0 + tn * 8);
    const float4 bb1 = *(const float4*)(bias + n0 + tn * 8 + 4);
#pragma unroll
    for (int i = 0; i < 8; i++) {
        float r0, r1, r2, r3, r4, r5, r6, r7;
        unpack2(acc[i][0], r0, r1);
        unpack2(acc[i][1], r2, r3);
        unpack2(acc[i][2], r4, r5);
        unpack2(acc[i][3], r6, r7);
        float* p = C + (size_t)(m0 + tm * 8 + i) * HD + n0 + tn * 8;
        *(float4*)p       = make_float4(r0 + bb0.x, r1 + bb0.y, r2 + bb0.z, r3 + bb0.w);
        *(float4*)(p + 4) = make_float4(r4 + bb1.x, r5 + bb1.y, r6 + bb1.z, r7 + bb1.w);
    }
}

// ---------------------------------------------------------------------------
// Kernel 2: persistent recurrence, DSMEM h-exchange, K-split-4, 256 threads.
//
// Grid: 16 clusters x 8 CTAs. Cluster y: batch rows [8y,8y+8). CTA x: hidden
// cols [64x,64x+64). Wh slice [512][64] resident in smem (loaded once).
//
// Per step:
//   1. thread (ksl,g) computes partials for 2 rows x 4 cols over k-slice
//      [128ksl, 128ksl+128) from duplicated Hs + resident Ws (FFMA2 floor).
//   2. smem reduction folds ksl 1..3 into ksl 0.
//   3. tid<64: + xw, tanh, STG out (fire-and-forget), export RAW h slice
//      (2KB, double-buffered).
//   4. barrier.cluster (release/acquire; no fence, no L1 flush).
//   5. warp w pulls rank w's raw 2KB via mapa + ld.shared::cluster and writes
//      it into Hs as duplicated float2 pairs. SKIPPED on the final step so no
//      CTA ever touches peer SMEM after the last barrier (exit hazard fix).
// ---------------------------------------------------------------------------
#define HROW   4112                       // Hs row stride bytes (514 float2)
#define WS_OFF 0
#define HS_OFF 131072                     // 512*64*4
#define EXP_OFF (HS_OFF + 8 * HROW)       // 163968
#define RED_OFF (EXP_OFF + 2 * 2048)      // 168064
#define SMEM_RNN_BYTES (RED_OFF + 8192)   // 176256

__global__ __launch_bounds__(256, 1) __cluster_dims__(8, 1, 1)
void rnn_persistent(const float* __restrict__ Wh,
                    const float* __restrict__ h0,
                    float* __restrict__ out)
{
    extern __shared__ char smem[];
    const uint32_t sbase = smem_u32(smem);

    const int tid = threadIdx.x;
    const int m0  = blockIdx.y * 8;
    const int n0  = blockIdx.x * 64;

    // ---- load Wh slice once: 512x64 floats = 8192 float4, 32/thread ----
#pragma unroll 4
    for (int j = 0; j < 32; j++) {
        int f  = tid + j * 256;
        int k  = f >> 4;
        int nq = f & 15;
        *(float4*)(smem + WS_OFF + ((size_t)k * 64 + nq * 4) * 4) =
            *(const float4*)(Wh + (size_t)k * HD + n0 + nq * 4);
    }

    // ---- stage h0 into Hs (duplicated pairs): 1024 float4, 4/thread ----
#pragma unroll
    for (int j = 0; j < 4; j++) {
        int f   = tid + j * 256;
        int row = f >> 7;
        int q   = f & 127;
        float4 v = *(const float4*)(h0 + (size_t)(m0 + row) * HD + q * 4);
        char* d = smem + HS_OFF + row * HROW + q * 32;
        *(float4*)d        = make_float4(v.x, v.x, v.y, v.y);
        *(float4*)(d + 16) = make_float4(v.z, v.z, v.w, v.w);
    }
    __syncthreads();

    // compute-thread decomposition
    const int ksl = tid >> 6;          // k-slice 0..3
    const int g   = tid & 63;
    const int rp  = g & 3;             // row pair 0..3
    const int cq  = g >> 2;            // col quad 0..15
    const int r0  = rp * 2;
    const int r1  = r0 + 1;
    const int c   = cq * 4;
    const int k0  = ksl * 128;

    const ull*   hr0 = (const ull*)(smem + HS_OFF + r0 * HROW);
    const ull*   hr1 = (const ull*)(smem + HS_OFF + r1 * HROW);
    const float* wc  = (const float*)(smem + WS_OFF) + c;

    // pull mapping: warp pw pulls rank pw's 2KB raw export.
    // lane -> (row = lane>>2, 64B part = lane&3); each lane: 4 x 16B loads.
    const int pw    = tid >> 5;
    const int lane  = tid & 31;
    const int prow  = lane >> 2;
    const int ppart = lane & 3;
    // Hs destination: float2 col base = pw*64 + ppart*16
    char* pdst = smem + HS_OFF + prow * HROW + ((size_t)pw * 64 + ppart * 16) * 8;

    for (int t = 0; t < TS; t++) {
        // xw prefetch (epilogue threads; LDG hidden behind the compute loop)
        float4 xw0 = make_float4(0.f, 0.f, 0.f, 0.f);
        float4 xw1 = xw0;
        float *pio0 = 0, *pio1 = 0;
        if (tid < 64) {
            pio0 = out + ((size_t)(m0 + r0) * TS + t) * HD + n0 + c;
            pio1 = out + ((size_t)(m0 + r1) * TS + t) * HD + n0 + c;
            xw0 = *(const float4*)pio0;
            xw1 = *(const float4*)pio1;
        }

        // ---- partial GEMM over this thread's k-slice ----
        ull a00 = 0ULL, a01 = 0ULL, a10 = 0ULL, a11 = 0ULL;
#pragma unroll 8
        for (int k = k0; k < k0 + 128; k++) {
            ull h0v = hr0[k];
            ull h1v = hr1[k];
            ulonglong2 w = *(const ulonglong2*)(wc + (size_t)k * 64);
            fma2(a00, h0v, w.x);
            fma2(a01, h0v, w.y);
            fma2(a10, h1v, w.x);
            fma2(a11, h1v, w.y);
        }

        // ---- K-split reduction: ksl 1..3 dump partials to smem ----
        if (ksl != 0) {
            char* rb = smem + RED_OFF + (size_t)tid * 32;
            *(ulonglong2*)rb        = make_ulonglong2(a00, a01);
            *(ulonglong2*)(rb + 16) = make_ulonglong2(a10, a11);
        }
        __syncthreads();

        if (tid < 64) {
#pragma unroll
            for (int s = 1; s < 4; s++) {
                char* rb = smem + RED_OFF + (size_t)(s * 64 + g) * 32;
                ulonglong2 p0 = *(const ulonglong2*)rb;
                ulonglong2 p1 = *(const ulonglong2*)(rb + 16);
                add2(a00, p0.x);
                add2(a01, p0.y);
                add2(a10, p1.x);
                add2(a11, p1.y);
            }
            float s00, s01, s02, s03, s10, s11, s12, s13;
            unpack2(a00, s00, s01);
            unpack2(a01, s02, s03);
            unpack2(a10, s10, s11);
            unpack2(a11, s12, s13);

            float4 hv0, hv1;
            hv0.x = tanhf(xw0.x + s00);
            hv0.y = tanhf(xw0.y + s01);
            hv0.z = tanhf(xw0.z + s02);
            hv0.w = tanhf(xw0.w + s03);
            hv1.x = tanhf(xw1.x + s10);
            hv1.y = tanhf(xw1.y + s11);
            hv1.z = tanhf(xw1.z + s12);
            hv1.w = tanhf(xw1.w + s13);

            // output (never re-read: no fence needed)
            *(float4*)pio0 = hv0;
            *(float4*)pio1 = hv1;

            // export RAW h slice (double-buffered, 2KB): row-major 8 x 256B
            char* eb = smem + EXP_OFF + (t & 1) * 2048;
            *(float4*)(eb + r0 * 256 + cq * 16) = hv0;
            *(float4*)(eb + r1 * 256 + cq * 16) = hv1;
        }

        // ---- cluster-wide exchange barrier (release/acquire) ----
        CLUSTER_ARRIVE();
        CLUSTER_WAIT();

        // ---- pull all 8 ranks' raw exports, duplicate into Hs ----
        // Skipped on the final step: after the last barrier no CTA may touch
        // peer SMEM (exit hazard), and nothing consumes Hs afterwards.
        if (t < TS - 1) {
            uint32_t src = mapa_rank(
                sbase + EXP_OFF + (t & 1) * 2048 + prow * 256 + ppart * 64, pw);
#pragma unroll
            for (int i = 0; i < 4; i++) {
                uint4 v = ld_cluster_v4(src + i * 16);
                float f0 = __uint_as_float(v.x);
                float f1 = __uint_as_float(v.y);
                float f2 = __uint_as_float(v.z);
                float f3 = __uint_as_float(v.w);
                char* d = pdst + i * 32;
                *(float4*)d        = make_float4(f0, f0, f1, f1);
                *(float4*)(d + 16) = make_float4(f2, f2, f3, f3);
            }
        }
        __syncthreads();
    }
}

// ---------------------------------------------------------------------------
// Launch
// ---------------------------------------------------------------------------
extern "C" void kernel_launch(void* const* d_in, const int* in_sizes, int n_in,
                              void* d_out, int out_size) {
    (void)in_sizes; (void)n_in; (void)out_size;
    const float* x  = (const float*)d_in[0];   // [128, 512, 512]
    const float* h0 = (const float*)d_in[1];   // [128, 512]
    const float* Wx = (const float*)d_in[2];   // [512, 512]
    const float* Wh = (const float*)d_in[3];   // [512, 512]
    const float* b  = (const float*)d_in[4];   // [512]
    float* out = (float*)d_out;                // [128, 512, 512]

    dim3 gx(HD / 128, (NB * TS) / 128);        // (4, 512)
    xw_gemm<<<gx, 256>>>(x, Wx, b, out);

    cudaFuncSetAttribute(rnn_persistent,
                         cudaFuncAttributeMaxDynamicSharedMemorySize,
                         SMEM_RNN_BYTES);
    dim3 gs(8, NB / 8);                        // 8 CTAs/cluster x 16 clusters
    rnn_persistent<<<gs, 256, SMEM_RNN_BYTES>>>(Wh, h0, out);
}

// round 12
// speedup vs baseline: 2.0338x; 1.1679x over previous
#include <cuda_runtime.h>
#include <math.h>
#include <stdint.h>

// Problem constants
#define NB 128   // batch
#define TS 512   // timesteps
#define DI 512   // input dim
#define HD 512   // hidden dim

typedef unsigned long long ull;

// ---------------- packed f32x2 helpers (sm_100+ FFMA2 path) ----------------
__device__ __forceinline__ void fma2(ull& acc, ull a, ull b) {
    asm("fma.rn.f32x2 %0, %1, %2, %0;" : "+l"(acc) : "l"(a), "l"(b));
}
__device__ __forceinline__ void add2(ull& a, ull b) {
    asm("add.rn.f32x2 %0, %0, %1;" : "+l"(a) : "l"(b));
}
__device__ __forceinline__ void unpack2(ull v, float& lo, float& hi) {
    unsigned int a, b;
    asm("mov.b64 {%0, %1}, %2;" : "=r"(a), "=r"(b) : "l"(v));
    lo = __uint_as_float(a);
    hi = __uint_as_float(b);
}

#define CLUSTER_ARRIVE() asm volatile("barrier.cluster.arrive.aligned;" ::: "memory")
#define CLUSTER_WAIT()   asm volatile("barrier.cluster.wait.aligned;" ::: "memory")

__device__ __forceinline__ uint32_t smem_u32(const void* p) {
    uint32_t a;
    asm("{ .reg .u64 t; cvta.to.shared.u64 t, %1; cvt.u32.u64 %0, t; }"
        : "=r"(a) : "l"(p));
    return a;
}
__device__ __forceinline__ uint32_t mapa_rank(uint32_t laddr, uint32_t rank) {
    uint32_t r;
    asm("mapa.shared::cluster.u32 %0, %1, %2;" : "=r"(r) : "r"(laddr), "r"(rank));
    return r;
}
__device__ __forceinline__ uint4 ld_cluster_v4(uint32_t addr) {
    uint4 v;
    asm volatile("ld.shared::cluster.v4.b32 {%0,%1,%2,%3}, [%4];"
                 : "=r"(v.x), "=r"(v.y), "=r"(v.z), "=r"(v.w) : "r"(addr));
    return v;
}

// ---------------------------------------------------------------------------
// Kernel 1: xW = x @ Wx + b  (unchanged — proven, rel_err 3.7e-7)
// ---------------------------------------------------------------------------
__global__ __launch_bounds__(256) void xw_gemm(
    const float* __restrict__ A,
    const float* __restrict__ B,
    const float* __restrict__ bias,
    float* __restrict__ C)
{
    __shared__ float2 As2[128][16];
    __shared__ float  Bs[16][128];

    const int m0  = blockIdx.y * 128;
    const int n0  = blockIdx.x * 128;
    const int tid = threadIdx.x;
    const int tn  = tid & 15;
    const int tm  = tid >> 4;

    ull acc[8][4];
#pragma unroll
    for (int i = 0; i < 8; i++)
#pragma unroll
        for (int j = 0; j < 4; j++) acc[i][j] = 0ULL;

    for (int k0 = 0; k0 < DI; k0 += 16) {
#pragma unroll
        for (int j = 0; j < 2; j++) {
            int f  = tid + j * 256;
            int m  = f >> 2;
            int kq = f & 3;
            float4 v = *(const float4*)(A + (size_t)(m0 + m) * DI + k0 + kq * 4);
            *(float4*)(&As2[m][kq * 4])     = make_float4(v.x, v.x, v.y, v.y);
            *(float4*)(&As2[m][kq * 4 + 2]) = make_float4(v.z, v.z, v.w, v.w);
        }
#pragma unroll
        for (int j = 0; j < 2; j++) {
            int f  = tid + j * 256;
            int k  = f >> 5;
            int nq = f & 31;
            *(float4*)(&Bs[k][nq * 4]) =
                *(const float4*)(B + (size_t)(k0 + k) * HD + n0 + nq * 4);
        }
        __syncthreads();

#pragma unroll
        for (int k = 0; k < 16; k++) {
            ulonglong2 b01 = *(const ulonglong2*)(&Bs[k][tn * 8]);
            ulonglong2 b23 = *(const ulonglong2*)(&Bs[k][tn * 8 + 4]);
#pragma unroll
            for (int i = 0; i < 8; i++) {
                ull a = *(const ull*)(&As2[tm * 8 + i][k]);
                fma2(acc[i][0], a, b01.x);
                fma2(acc[i][1], a, b01.y);
                fma2(acc[i][2], a, b23.x);
                fma2(acc[i][3], a, b23.y);
            }
        }
        __syncthreads();
    }

    const float4 bb0 = *(const float4*)(bias + n0 + tn * 8);
    const float4 bb1 = *(const float4*)(bias + n0 + tn * 8 + 4);
#pragma unroll
    for (int i = 0; i < 8; i++) {
        float r0, r1, r2, r3, r4, r5, r6, r7;
        unpack2(acc[i][0], r0, r1);
        unpack2(acc[i][1], r2, r3);
        unpack2(acc[i][2], r4, r5);
        unpack2(acc[i][3], r6, r7);
        float* p = C + (size_t)(m0 + tm * 8 + i) * HD + n0 + tn * 8;
        *(float4*)p       = make_float4(r0 + bb0.x, r1 + bb0.y, r2 + bb0.z, r3 + bb0.w);
        *(float4*)(p + 4) = make_float4(r4 + bb1.x, r5 + bb1.y, r6 + bb1.z, r7 + bb1.w);
    }
}

// ---------------------------------------------------------------------------
// Kernel 2: persistent recurrence, DSMEM h-exchange, register-blocked GEMM.
//
// Grid: 16 clusters x 8 CTAs. Cluster y: batch rows [8y,8y+8). CTA x: hidden
// cols [64x,64x+64). Wh slice [512][64] resident in smem (loaded once).
//
// Compute (crossbar-byte optimized): thread (ks,g) = k-slice ks (32 k) and
// g -> (rh = g&1 -> rows rh*4..+4, co = g>>1 -> cols co*8..+8). Per k:
// 4x LDS.64 (h dup) + 2x LDS.128 (w) = 64 B delivered for 16 FFMA2
// (4 B/FFMA2; the R10 loop was 8). Crossbar/step/SM: 512KB -> ~4096 cyc.
//
// Reduction: 16 partials per f32x2 slot; swizzled layout
// addr = slot*128 + ((ks+slot)&15)*8 makes the per-slot gather contiguous.
// Thread u finalizes slot u: +xw, tanh, STG.64 out, raw float2 export.
// Exchange: double-buffered 2KB raw export, one barrier.cluster, warp pw
// pulls rank pw via mapa+ld.shared::cluster, duplicates into Hs. Pull is
// skipped on the final step (exit hazard).
// ---------------------------------------------------------------------------
#define HROW   4112                       // Hs row stride bytes (514 float2)
#define WS_OFF 0
#define HS_OFF 131072                     // 512*64*4
#define EXP_OFF (HS_OFF + 8 * HROW)       // 163968
#define RED_OFF (EXP_OFF + 2 * 2048)      // 168064
#define SMEM_RNN_BYTES (RED_OFF + 32768)  // 200832

__global__ __launch_bounds__(256, 1) __cluster_dims__(8, 1, 1)
void rnn_persistent(const float* __restrict__ Wh,
                    const float* __restrict__ h0,
                    float* __restrict__ out)
{
    extern __shared__ char smem[];
    const uint32_t sbase = smem_u32(smem);

    const int tid = threadIdx.x;
    const int m0  = blockIdx.y * 8;
    const int n0  = blockIdx.x * 64;

    // ---- load Wh slice once: 512x64 floats = 8192 float4, 32/thread ----
#pragma unroll 4
    for (int j = 0; j < 32; j++) {
        int f  = tid + j * 256;
        int k  = f >> 4;
        int nq = f & 15;
        *(float4*)(smem + WS_OFF + ((size_t)k * 64 + nq * 4) * 4) =
            *(const float4*)(Wh + (size_t)k * HD + n0 + nq * 4);
    }

    // ---- stage h0 into Hs (duplicated pairs): 1024 float4, 4/thread ----
#pragma unroll
    for (int j = 0; j < 4; j++) {
        int f   = tid + j * 256;
        int row = f >> 7;
        int q   = f & 127;
        float4 v = *(const float4*)(h0 + (size_t)(m0 + row) * HD + q * 4);
        char* d = smem + HS_OFF + row * HROW + q * 32;
        *(float4*)d        = make_float4(v.x, v.x, v.y, v.y);
        *(float4*)(d + 16) = make_float4(v.z, v.z, v.w, v.w);
    }
    __syncthreads();

    // compute-thread decomposition: 16 k-slices x (2 row-halves x 8 col-octs)
    const int ks = tid >> 4;           // k-slice 0..15 (32 k each)
    const int g  = tid & 15;
    const int rh = g & 1;              // row half: rows rh*4 .. rh*4+3
    const int co = g >> 1;             // col oct:  cols co*8 .. co*8+7
    const int kbeg = ks * 32;

    const char* hbase = smem + HS_OFF + (rh * 4) * HROW;
    const char* wbase = smem + WS_OFF + co * 32;

    // reduction slot for this thread (one f32x2 output): row u>>5, colpair u&31
    const int r  = tid >> 5;
    const int cp = tid & 31;

    // pull mapping: warp pw pulls rank pw's 2KB raw export.
    const int pw    = tid >> 5;
    const int lane  = tid & 31;
    const int prow  = lane >> 2;
    const int ppart = lane & 3;
    char* pdst = smem + HS_OFF + prow * HROW + ((size_t)pw * 64 + ppart * 16) * 8;

    for (int t = 0; t < TS; t++) {
        // xw prefetch for this thread's slot (LDG hidden behind compute loop)
        float* pio = out + ((size_t)(m0 + r) * TS + t) * HD + n0 + cp * 2;
        float2 xw = *(const float2*)pio;

        // ---- register-blocked partial GEMM: 4 rows x 8 cols, 32 k ----
        ull acc[4][4];
#pragma unroll
        for (int i = 0; i < 4; i++)
#pragma unroll
            for (int j = 0; j < 4; j++) acc[i][j] = 0ULL;

#pragma unroll 8
        for (int kk = 0; kk < 32; kk++) {
            const int k = kbeg + kk;
            ull h0v = *(const ull*)(hbase + k * 8);
            ull h1v = *(const ull*)(hbase + HROW + k * 8);
            ull h2v = *(const ull*)(hbase + 2 * HROW + k * 8);
            ull h3v = *(const ull*)(hbase + 3 * HROW + k * 8);
            ulonglong2 w01 = *(const ulonglong2*)(wbase + (size_t)k * 256);
            ulonglong2 w23 = *(const ulonglong2*)(wbase + (size_t)k * 256 + 16);
            fma2(acc[0][0], h0v, w01.x); fma2(acc[0][1], h0v, w01.y);
            fma2(acc[0][2], h0v, w23.x); fma2(acc[0][3], h0v, w23.y);
            fma2(acc[1][0], h1v, w01.x); fma2(acc[1][1], h1v, w01.y);
            fma2(acc[1][2], h1v, w23.x); fma2(acc[1][3], h1v, w23.y);
            fma2(acc[2][0], h2v, w01.x); fma2(acc[2][1], h2v, w01.y);
            fma2(acc[2][2], h2v, w23.x); fma2(acc[2][3], h2v, w23.y);
            fma2(acc[3][0], h3v, w01.x); fma2(acc[3][1], h3v, w01.y);
            fma2(acc[3][2], h3v, w23.x); fma2(acc[3][3], h3v, w23.y);
        }

        // ---- store partials (swizzled: addr = slot*128 + ((ks+slot)&15)*8) ----
#pragma unroll
        for (int i = 0; i < 4; i++) {
#pragma unroll
            for (int j = 0; j < 4; j++) {
                int slot = ((rh * 4 + i) << 5) | (co * 4 + j);
                *(ull*)(smem + RED_OFF + slot * 128 + (((ks + slot) & 15) << 3))
                    = acc[i][j];
            }
        }
        __syncthreads();

        // ---- per-slot reduction over 16 k-slices + epilogue (all threads) ----
        {
            const char* rb = smem + RED_OFF + tid * 128;
            ull s = *(const ull*)(rb + ((tid & 15) << 3));
#pragma unroll
            for (int kss = 1; kss < 16; kss++)
                add2(s, *(const ull*)(rb + (((kss + tid) & 15) << 3)));

            float slo, shi;
            unpack2(s, slo, shi);
            float2 hv;
            hv.x = tanhf(xw.x + slo);
            hv.y = tanhf(xw.y + shi);

            // output (never re-read: no fence needed)
            *(float2*)pio = hv;

            // export RAW h slot (double-buffered, 2KB): row-major 8 x 256B
            *(float2*)(smem + EXP_OFF + (t & 1) * 2048 + r * 256 + cp * 8) = hv;
        }

        // ---- cluster-wide exchange barrier (release/acquire) ----
        CLUSTER_ARRIVE();
        CLUSTER_WAIT();

        // ---- pull all 8 ranks' raw exports, duplicate into Hs ----
        // Skipped on the final step: no CTA may touch peer SMEM after the
        // last barrier (exit hazard), and nothing consumes Hs afterwards.
        if (t < TS - 1) {
            uint32_t src = mapa_rank(
                sbase + EXP_OFF + (t & 1) * 2048 + prow * 256 + ppart * 64, pw);
#pragma unroll
            for (int i = 0; i < 4; i++) {
                uint4 v = ld_cluster_v4(src + i * 16);
                float f0 = __uint_as_float(v.x);
                float f1 = __uint_as_float(v.y);
                float f2 = __uint_as_float(v.z);
                float f3 = __uint_as_float(v.w);
                char* d = pdst + i * 32;
                *(float4*)d        = make_float4(f0, f0, f1, f1);
                *(float4*)(d + 16) = make_float4(f2, f2, f3, f3);
            }
        }
        __syncthreads();
    }
}

// ---------------------------------------------------------------------------
// Launch
// ---------------------------------------------------------------------------
extern "C" void kernel_launch(void* const* d_in, const int* in_sizes, int n_in,
                              void* d_out, int out_size) {
    (void)in_sizes; (void)n_in; (void)out_size;
    const float* x  = (const float*)d_in[0];   // [128, 512, 512]
    const float* h0 = (const float*)d_in[1];   // [128, 512]
    const float* Wx = (const float*)d_in[2];   // [512, 512]
    const float* Wh = (const float*)d_in[3];   // [512, 512]
    const float* b  = (const float*)d_in[4];   // [512]
    float* out = (float*)d_out;                // [128, 512, 512]

    dim3 gx(HD / 128, (NB * TS) / 128);        // (4, 512)
    xw_gemm<<<gx, 256>>>(x, Wx, b, out);

    cudaFuncSetAttribute(rnn_persistent,
                         cudaFuncAttributeMaxDynamicSharedMemorySize,
                         SMEM_RNN_BYTES);
    dim3 gs(8, NB / 8);                        // 8 CTAs/cluster x 16 clusters
    rnn_persistent<<<gs, 256, SMEM_RNN_BYTES>>>(Wh, h0, out);
}